// round 6
// baseline (speedup 1.0000x reference)
#include <cuda_runtime.h>
#include <cstdint>
#include <mma.h>

using namespace nvcuda;

namespace {
constexpr int B  = 2;
constexpr int S  = 2048;
constexpr int E  = 1024;
constexpr int H  = 16;
constexpr int DH = 64;
constexpr int M  = B * S;    // 4096
constexpr int BH = B * H;    // 32
constexpr long long OUT_ELEMS = (long long)B * S * E;
constexpr long long W_ELEMS   = (long long)B * H * S * S;
constexpr float ATTN_SCALE = 0.125f;

constexpr int BQ  = 128;     // q rows per block
constexpr int BK  = 64;      // k cols per tile
constexpr int NKT = S / BK;  // 32
constexpr int LD  = 68;      // smem stride (64 + 4 pad)
}

// Scratch
__device__ float g_qh[(long long)BH * S * DH];
__device__ float g_kh[(long long)BH * S * DH];
__device__ float g_vh[(long long)BH * S * DH];
__device__ float g_att[(long long)M * E];
__device__ float g_wfallback[W_ELEMS];

__device__ __forceinline__ float tf32r(float x) { return wmma::__float_to_tf32(x); }

__device__ __forceinline__ void cp_async16(unsigned dst, const float* src) {
    asm volatile("cp.async.cg.shared.global [%0], [%1], 16;\n" :: "r"(dst), "l"(src));
}
__device__ __forceinline__ void cp_commit() {
    asm volatile("cp.async.commit_group;\n" ::: "memory");
}
template <int N>
__device__ __forceinline__ void cp_wait() {
    asm volatile("cp.async.wait_group %0;\n" :: "n"(N) : "memory");
}

// ---------------------------------------------------------------------------
// Projection GEMM: out = (X @ Wt^T + bias) * scale. tf32 rounding at staging.
// Modes 0/1/2 additionally tf32-round the OUTPUT (so attn can cp.async raw).
// ---------------------------------------------------------------------------
__global__ void __launch_bounds__(256)
gemm_tf32_kernel(const float* __restrict__ Ain, const float* __restrict__ Wt,
                 const float* __restrict__ bias, float scale,
                 int mode, float* __restrict__ outFlat)
{
    __shared__ __align__(16) float As[128][36];
    __shared__ __align__(16) float Bs[128][36];
    __shared__ __align__(16) float scr[8][16 * 20];

    const float* Aeff = (mode == 3) ? g_att : Ain;

    const int bm = blockIdx.y * 128;
    const int bn = blockIdx.x * 128;
    const int tid  = threadIdx.x;
    const int warp = tid >> 5;
    const int lane = tid & 31;
    const int warpM = warp >> 2;
    const int warpN = warp & 3;

    wmma::fragment<wmma::accumulator, 16, 16, 8, float> c[4][2];
    #pragma unroll
    for (int mi = 0; mi < 4; ++mi)
        #pragma unroll
        for (int ni = 0; ni < 2; ++ni)
            wmma::fill_fragment(c[mi][ni], 0.0f);

    for (int k0 = 0; k0 < E; k0 += 32) {
        #pragma unroll
        for (int i = tid; i < 128 * 8; i += 256) {
            const int r = i >> 3, c4 = i & 7;
            float4 av = *(const float4*)&Aeff[(size_t)(bm + r) * E + k0 + c4 * 4];
            float4 bv = *(const float4*)&Wt[(size_t)(bn + r) * E + k0 + c4 * 4];
            av.x = tf32r(av.x); av.y = tf32r(av.y); av.z = tf32r(av.z); av.w = tf32r(av.w);
            bv.x = tf32r(bv.x); bv.y = tf32r(bv.y); bv.z = tf32r(bv.z); bv.w = tf32r(bv.w);
            *(float4*)&As[r][c4 * 4] = av;
            *(float4*)&Bs[r][c4 * 4] = bv;
        }
        __syncthreads();

        #pragma unroll
        for (int kc = 0; kc < 4; ++kc) {
            wmma::fragment<wmma::matrix_a, 16, 16, 8, wmma::precision::tf32, wmma::row_major> a[4];
            wmma::fragment<wmma::matrix_b, 16, 16, 8, wmma::precision::tf32, wmma::col_major> b[2];
            #pragma unroll
            for (int mi = 0; mi < 4; ++mi)
                wmma::load_matrix_sync(a[mi], &As[warpM * 64 + mi * 16][kc * 8], 36);
            #pragma unroll
            for (int ni = 0; ni < 2; ++ni)
                wmma::load_matrix_sync(b[ni], &Bs[warpN * 32 + ni * 16][kc * 8], 36);
            #pragma unroll
            for (int mi = 0; mi < 4; ++mi)
                #pragma unroll
                for (int ni = 0; ni < 2; ++ni)
                    wmma::mma_sync(c[mi][ni], a[mi], b[ni], c[mi][ni]);
        }
        __syncthreads();
    }

    float* outHeads = (mode == 0) ? g_qh : (mode == 1) ? g_kh : g_vh;

    #pragma unroll
    for (int mi = 0; mi < 4; ++mi) {
        #pragma unroll
        for (int ni = 0; ni < 2; ++ni) {
            wmma::store_matrix_sync(&scr[warp][0], c[mi][ni], 20, wmma::mem_row_major);
            __syncwarp();
            const int m0 = bm + warpM * 64 + mi * 16;
            const int n0 = bn + warpN * 32 + ni * 16;
            #pragma unroll
            for (int it = 0; it < 8; ++it) {
                const int idx = lane + it * 32;
                const int r = idx >> 4, cc = idx & 15;
                const int m = m0 + r;
                const int n = n0 + cc;
                const float v = (scr[warp][r * 20 + cc] + bias[n]) * scale;
                if (mode == 3) {
                    outFlat[(size_t)m * E + n] = v;
                } else {
                    const int b_ = m >> 11, s_ = m & (S - 1);
                    const int h_ = n >> 6,  d_ = n & 63;
                    outHeads[(((size_t)(b_ * H + h_)) * S + s_) * DH + d_] = tf32r(v);
                }
            }
            __syncwarp();
        }
    }
}

// ---------------------------------------------------------------------------
// Single-pass fused attention, software-pipelined:
//   K_t consumed by QK while V_t streams in (cp.async);
//   V_t consumed by PV while K_{t+1} streams in.
//   p~ = exp(S) written unnormalized; epilogue fixup scales by 1/l.
// ---------------------------------------------------------------------------
struct AttnSmem {
    float Q[BQ][LD];     // 34816 B
    float K[BK][LD];     // 17408 B
    float V[BK][LD];     // 17408 B  (row-major [k][d])
    float P[BQ][LD];     // 34816 B
    float l[BQ];
    float invl[BQ];
};

__global__ void __launch_bounds__(256, 2)
attn_fused_kernel(float* __restrict__ outw, int use_fb)
{
    extern __shared__ __align__(16) char smem_raw[];
    AttnSmem* sm = (AttnSmem*)smem_raw;

    float* wts = use_fb ? g_wfallback : outw;

    const int q0 = blockIdx.x * BQ;
    const int bh = blockIdx.y;
    const float* Qg = g_qh + (size_t)bh * S * DH;
    const float* Kg = g_kh + (size_t)bh * S * DH;
    const float* Vg = g_vh + (size_t)bh * S * DH;
    float* Wb = wts + (size_t)bh * S * S;

    const int tid  = threadIdx.x;
    const int warp = tid >> 5;          // 0..7 -> 16-row slice
    const int grp  = tid >> 4;          // 0..15
    const int gln  = tid & 15;

    const unsigned smQ = (unsigned)__cvta_generic_to_shared(&sm->Q[0][0]);
    const unsigned smK = (unsigned)__cvta_generic_to_shared(&sm->K[0][0]);
    const unsigned smV = (unsigned)__cvta_generic_to_shared(&sm->V[0][0]);

    // --- stage Q (cp.async; values already tf32-rounded in gmem) + K_0 ---
    #pragma unroll
    for (int i = tid; i < BQ * 16; i += 256) {
        const int r = i >> 4, c4 = i & 15;
        cp_async16(smQ + (unsigned)(r * LD + c4 * 4) * 4,
                   Qg + (size_t)(q0 + r) * DH + c4 * 4);
    }
    #pragma unroll
    for (int i = tid; i < BK * 16; i += 256) {
        const int r = i >> 4, c4 = i & 15;
        cp_async16(smK + (unsigned)(r * LD + c4 * 4) * 4,
                   Kg + (size_t)r * DH + c4 * 4);
    }
    cp_commit();
    if (tid < BQ) sm->l[tid] = 0.0f;
    cp_wait<0>();
    __syncthreads();

    // persistent PV accumulators: warp covers 16 rows x 64 cols
    wmma::fragment<wmma::accumulator, 16, 16, 8, float> o[4];
    #pragma unroll
    for (int ni = 0; ni < 4; ++ni) wmma::fill_fragment(o[ni], 0.0f);

    for (int kt = 0; kt < NKT; ++kt) {
        // issue V_t (group A)
        #pragma unroll
        for (int i = tid; i < BK * 16; i += 256) {
            const int r = i >> 4, c4 = i & 15;
            cp_async16(smV + (unsigned)(r * LD + c4 * 4) * 4,
                       Vg + (size_t)(kt * BK + r) * DH + c4 * 4);
        }
        cp_commit();

        // --- QK MMA: 128x64, warp = 16 rows x 64 cols ---
        {
            wmma::fragment<wmma::accumulator, 16, 16, 8, float> c[4];
            #pragma unroll
            for (int ni = 0; ni < 4; ++ni) wmma::fill_fragment(c[ni], 0.0f);
            #pragma unroll
            for (int kc = 0; kc < 8; ++kc) {
                wmma::fragment<wmma::matrix_a, 16, 16, 8, wmma::precision::tf32, wmma::row_major> a;
                wmma::load_matrix_sync(a, &sm->Q[warp * 16][kc * 8], LD);
                #pragma unroll
                for (int ni = 0; ni < 4; ++ni) {
                    wmma::fragment<wmma::matrix_b, 16, 16, 8, wmma::precision::tf32, wmma::col_major> b;
                    wmma::load_matrix_sync(b, &sm->K[ni * 16][kc * 8], LD);
                    wmma::mma_sync(c[ni], a, b, c[ni]);
                }
            }
            #pragma unroll
            for (int ni = 0; ni < 4; ++ni)
                wmma::store_matrix_sync(&sm->P[warp * 16][ni * 16], c[ni], LD,
                                        wmma::mem_row_major);
        }
        __syncthreads();

        // issue K_{t+1} (group B) — K buffer free after the sync above
        if (kt + 1 < NKT) {
            #pragma unroll
            for (int i = tid; i < BK * 16; i += 256) {
                const int r = i >> 4, c4 = i & 15;
                cp_async16(smK + (unsigned)(r * LD + c4 * 4) * 4,
                           Kg + (size_t)((kt + 1) * BK + r) * DH + c4 * 4);
            }
        }
        cp_commit();

        // --- exp + rowsum + gmem p~ write + tf32 round-back ---
        {
            #pragma unroll
            for (int p = 0; p < 8; ++p) {
                const int r = grp + p * 16;
                float4 t = *(float4*)&sm->P[r][gln * 4];
                t.x = __expf(fminf(t.x, 60.f));
                t.y = __expf(fminf(t.y, 60.f));
                t.z = __expf(fminf(t.z, 60.f));
                t.w = __expf(fminf(t.w, 60.f));
                *(float4*)&Wb[(size_t)(q0 + r) * S + kt * BK + gln * 4] = t;
                float rs = t.x + t.y + t.z + t.w;
                t.x = tf32r(t.x); t.y = tf32r(t.y); t.z = tf32r(t.z); t.w = tf32r(t.w);
                *(float4*)&sm->P[r][gln * 4] = t;
                #pragma unroll
                for (int o_ = 8; o_; o_ >>= 1)
                    rs += __shfl_xor_sync(0xffffffffu, rs, o_);
                if (gln == 0) sm->l[r] += rs;
            }
        }
        cp_wait<1>();     // V_t complete (older group)
        __syncthreads();

        // --- PV MMA: o += P(128x64) @ V(64x64), V row-major B ---
        #pragma unroll
        for (int kc = 0; kc < 8; ++kc) {
            wmma::fragment<wmma::matrix_a, 16, 16, 8, wmma::precision::tf32, wmma::row_major> a;
            wmma::load_matrix_sync(a, &sm->P[warp * 16][kc * 8], LD);
            #pragma unroll
            for (int ni = 0; ni < 4; ++ni) {
                wmma::fragment<wmma::matrix_b, 16, 16, 8, wmma::precision::tf32, wmma::row_major> b;
                wmma::load_matrix_sync(b, &sm->V[kc * 8][ni * 16], LD);
                wmma::mma_sync(o[ni], a, b, o[ni]);
            }
        }
        cp_wait<0>();     // K_{t+1} complete
        __syncthreads();
    }

    // --- inv_l ---
    if (tid < BQ) sm->invl[tid] = 1.0f / sm->l[tid];
    __syncthreads();

    // --- fixup: scale this CTA's probs strip by inv_l ---
    for (int i = tid; i < BQ * (S / 4); i += 256) {
        const int r = i >> 9, c4 = i & 511;
        const float s = sm->invl[r];
        float* p = &Wb[(size_t)(q0 + r) * S + c4 * 4];
        float4 t = *(float4*)p;
        t.x *= s; t.y *= s; t.z *= s; t.w *= s;
        *(float4*)p = t;
    }

    // --- O: frags -> smem -> scaled scatter to g_att ---
    #pragma unroll
    for (int ni = 0; ni < 4; ++ni)
        wmma::store_matrix_sync(&sm->P[warp * 16][ni * 16], o[ni], LD,
                                wmma::mem_row_major);
    __syncthreads();

    const int b_ = bh >> 4, h_ = bh & 15;
    for (int i = tid; i < BQ * 16; i += 256) {
        const int r = i >> 4, c4 = i & 15;
        const float s = sm->invl[r];
        float4 t = *(float4*)&sm->P[r][c4 * 4];
        t.x *= s; t.y *= s; t.z *= s; t.w *= s;
        *(float4*)&g_att[((size_t)(b_ * S + q0 + r)) * E + h_ * DH + c4 * 4] = t;
    }
}

// ---------------------------------------------------------------------------
extern "C" void kernel_launch(void* const* d_in, const int* in_sizes, int n_in,
                              void* d_out, int out_size)
{
    const float* q  = (const float*)d_in[0];
    const float* k  = (const float*)d_in[1];
    const float* v  = (const float*)d_in[2];
    const float* Wq = (const float*)d_in[3];
    const float* bq = (const float*)d_in[4];
    const float* Wk = (const float*)d_in[5];
    const float* bk = (const float*)d_in[6];
    const float* Wv = (const float*)d_in[7];
    const float* bv = (const float*)d_in[8];
    const float* Wo = (const float*)d_in[9];
    const float* bo = (const float*)d_in[10];
    float* out = (float*)d_out;

    const int use_fb = ((long long)out_size < OUT_ELEMS + W_ELEMS) ? 1 : 0;
    float* outw = out + OUT_ELEMS;

    static int smem_set = 0;
    const int attn_smem = (int)sizeof(AttnSmem);
    if (!smem_set) {
        cudaFuncSetAttribute(attn_fused_kernel,
                             cudaFuncAttributeMaxDynamicSharedMemorySize, attn_smem);
        smem_set = 1;
    }

    const dim3 blk(256);
    const dim3 gemm_grid(E / 128, M / 128);

    gemm_tf32_kernel<<<gemm_grid, blk>>>(q, Wq, bq, ATTN_SCALE, 0, nullptr);
    gemm_tf32_kernel<<<gemm_grid, blk>>>(k, Wk, bk, 1.0f,       1, nullptr);
    gemm_tf32_kernel<<<gemm_grid, blk>>>(v, Wv, bv, 1.0f,       2, nullptr);

    attn_fused_kernel<<<dim3(S / BQ, BH), blk, attn_smem>>>(outw, use_fb);

    gemm_tf32_kernel<<<gemm_grid, blk>>>(nullptr, Wo, bo, 1.0f, 3, out);
}